// round 2
// baseline (speedup 1.0000x reference)
#include <cuda_runtime.h>
#include <math.h>
#include <stdint.h>

#define QROWS 4096
#define DIM   512
#define TWO_D 1024
#define NKEYS 32768
#define TOPK  64
#define EPSF  1e-8f
#define NBINS 2048
#define CAP   1024

// ---------------- scratch (no allocations allowed) ----------------
__device__ float  g_q[(size_t)QROWS * TWO_D];        // projected q, interleaved [Q, D, 2]
__device__ double g_qmagd[QROWS];
__device__ float  g_qmagf[QROWS];
__device__ double g_kmagd[NKEYS];
__device__ float  g_kmagf[NKEYS];
__device__ float  g_scores[(size_t)QROWS * NKEYS];   // 512 MB coherence matrix
__device__ float  g_ret[(size_t)QROWS * TWO_D];      // retrieved
__device__ float  g_norm[(size_t)QROWS * TWO_D];     // phase-normed

// Kahan add, rounding-mode-pinned so fast-math/contraction cannot break it
__device__ __forceinline__ void kadd(float& s, float& c, float t) {
    float y = __fsub_rn(t, c);
    float u = __fadd_rn(s, y);
    c = __fsub_rn(__fsub_rn(u, s), y);
    s = u;
}

// ---------------- complex projection: Y = phase_linear(X, W, b) ----------------
// X:[Q,D,2], Wr/Wi:[D,D] (x @ W^T), Y:[Q,D,2].  PRECISE=true -> Kahan accumulation.
template <bool PRECISE>
__global__ void __launch_bounds__(256)
cproj_kernel(const float* __restrict__ X,
             const float* __restrict__ Wr, const float* __restrict__ Wi,
             const float* __restrict__ br, const float* __restrict__ bi,
             float* __restrict__ Y)
{
    __shared__ float2 Xs[16][64];
    __shared__ float2 Ws[16][64];
    const int tid = threadIdx.x;
    const int m0 = blockIdx.y * 64;
    const int n0 = blockIdx.x * 64;
    const int kk = tid & 15;
    const int rr = tid >> 4;
    const int ty4 = (tid >> 4) * 4;
    const int tx4 = (tid & 15) * 4;

    float cr[4][4], ci[4][4], er[4][4], ei[4][4];
#pragma unroll
    for (int i = 0; i < 4; i++)
#pragma unroll
        for (int j = 0; j < 4; j++) { cr[i][j] = 0.f; ci[i][j] = 0.f; er[i][j] = 0.f; ei[i][j] = 0.f; }

    for (int k0 = 0; k0 < DIM; k0 += 16) {
#pragma unroll
        for (int r = 0; r < 4; r++) {
            int row = rr + r * 16;
            Xs[kk][row] = *(const float2*)&X[((size_t)(m0 + row) * DIM + k0 + kk) * 2];
            float wr = Wr[(size_t)(n0 + row) * DIM + k0 + kk];
            float wi = Wi[(size_t)(n0 + row) * DIM + k0 + kk];
            Ws[kk][row] = make_float2(wr, wi);
        }
        __syncthreads();
#pragma unroll
        for (int k = 0; k < 16; k++) {
            float2 a[4], w[4];
#pragma unroll
            for (int i = 0; i < 4; i++) a[i] = Xs[k][ty4 + i];
#pragma unroll
            for (int j = 0; j < 4; j++) w[j] = Ws[k][tx4 + j];
#pragma unroll
            for (int i = 0; i < 4; i++)
#pragma unroll
                for (int j = 0; j < 4; j++) {
                    if (PRECISE) {
                        kadd(cr[i][j], er[i][j],  __fmul_rn(a[i].x, w[j].x));
                        kadd(cr[i][j], er[i][j], -__fmul_rn(a[i].y, w[j].y));
                        kadd(ci[i][j], ei[i][j],  __fmul_rn(a[i].x, w[j].y));
                        kadd(ci[i][j], ei[i][j],  __fmul_rn(a[i].y, w[j].x));
                    } else {
                        cr[i][j] += a[i].x * w[j].x;
                        cr[i][j] -= a[i].y * w[j].y;
                        ci[i][j] += a[i].x * w[j].y;
                        ci[i][j] += a[i].y * w[j].x;
                    }
                }
        }
        __syncthreads();
    }
#pragma unroll
    for (int i = 0; i < 4; i++) {
        int m = m0 + ty4 + i;
#pragma unroll
        for (int j = 0; j < 4; j++) {
            int n = n0 + tx4 + j;
            float vr = PRECISE ? __fadd_rn(cr[i][j], er[i][j]) : cr[i][j];
            float vi = PRECISE ? __fadd_rn(ci[i][j], ei[i][j]) : ci[i][j];
            Y[((size_t)m * DIM + n) * 2 + 0] = vr + br[n];
            Y[((size_t)m * DIM + n) * 2 + 1] = vi + bi[n];
        }
    }
}

// ---------------- magnitude (double): sqrt(sum x^2 + EPS) ----------------
__global__ void magd_kernel(const float* __restrict__ X,
                            double* __restrict__ out_d, float* __restrict__ out_f)
{
    __shared__ double sm[128];
    int row = blockIdx.x;
    const float* p = X + (size_t)row * TWO_D;
    double s = 0.0;
    for (int i = threadIdx.x; i < TWO_D; i += 128) { double v = (double)p[i]; s += v * v; }
    sm[threadIdx.x] = s;
    __syncthreads();
    for (int o = 64; o > 0; o >>= 1) {
        if (threadIdx.x < o) sm[threadIdx.x] += sm[threadIdx.x + o];
        __syncthreads();
    }
    if (threadIdx.x == 0) {
        double m = sqrt(sm[0] + 1e-8);
        out_d[row] = m;
        out_f[row] = (float)m;
    }
}

// ---------------- screening coherence GEMM (fp32; feeds candidate selection only) --------
__global__ void __launch_bounds__(256, 2)
coh_gemm_kernel(const float* __restrict__ A,   // [QROWS, 1024]
                const float* __restrict__ B,   // [NKEYS, 1024]
                const float* __restrict__ qmag,
                const float* __restrict__ kmag,
                float* __restrict__ C)
{
    __shared__ float As[16][128];
    __shared__ float Bs[16][128];
    const int tid = threadIdx.x;
    const int m0 = blockIdx.y * 128;
    const int n0 = blockIdx.x * 128;
    const int tx = tid & 15;
    const int ty = tid >> 4;
    const int lr = tid >> 2;
    const int lc = (tid & 3) << 2;

    const float* Ab = A + (size_t)(m0 + lr) * TWO_D + lc;
    const float* Bb = B + (size_t)(n0 + lr) * TWO_D + lc;

    float acc[8][8];
#pragma unroll
    for (int i = 0; i < 8; i++)
#pragma unroll
        for (int j = 0; j < 8; j++) acc[i][j] = 0.f;

    for (int k0 = 0; k0 < TWO_D; k0 += 16) {
        float4 a0 = *(const float4*)(Ab + k0);
        float4 a1 = *(const float4*)(Ab + (size_t)64 * TWO_D + k0);
        float4 b0 = *(const float4*)(Bb + k0);
        float4 b1 = *(const float4*)(Bb + (size_t)64 * TWO_D + k0);
        As[lc + 0][lr] = a0.x; As[lc + 1][lr] = a0.y; As[lc + 2][lr] = a0.z; As[lc + 3][lr] = a0.w;
        As[lc + 0][lr + 64] = a1.x; As[lc + 1][lr + 64] = a1.y; As[lc + 2][lr + 64] = a1.z; As[lc + 3][lr + 64] = a1.w;
        Bs[lc + 0][lr] = b0.x; Bs[lc + 1][lr] = b0.y; Bs[lc + 2][lr] = b0.z; Bs[lc + 3][lr] = b0.w;
        Bs[lc + 0][lr + 64] = b1.x; Bs[lc + 1][lr + 64] = b1.y; Bs[lc + 2][lr + 64] = b1.z; Bs[lc + 3][lr + 64] = b1.w;
        __syncthreads();
#pragma unroll
        for (int k = 0; k < 16; k++) {
            float ar[8], bc[8];
            *(float4*)(ar)     = *(const float4*)&As[k][ty * 8];
            *(float4*)(ar + 4) = *(const float4*)&As[k][ty * 8 + 4];
            *(float4*)(bc)     = *(const float4*)&Bs[k][tx * 8];
            *(float4*)(bc + 4) = *(const float4*)&Bs[k][tx * 8 + 4];
#pragma unroll
            for (int i = 0; i < 8; i++)
#pragma unroll
                for (int j = 0; j < 8; j++)
                    acc[i][j] += ar[i] * bc[j];
        }
        __syncthreads();
    }

    float qm[8], km[8];
#pragma unroll
    for (int i = 0; i < 8; i++) qm[i] = qmag[m0 + ty * 8 + i];
#pragma unroll
    for (int j = 0; j < 8; j++) km[j] = kmag[n0 + tx * 8 + j];
#pragma unroll
    for (int i = 0; i < 8; i++) {
        size_t base = (size_t)(m0 + ty * 8 + i) * NKEYS + n0 + tx * 8;
        float4 o0, o1;
        o0.x = acc[i][0] / (qm[i] * km[0] + EPSF);
        o0.y = acc[i][1] / (qm[i] * km[1] + EPSF);
        o0.z = acc[i][2] / (qm[i] * km[2] + EPSF);
        o0.w = acc[i][3] / (qm[i] * km[3] + EPSF);
        o1.x = acc[i][4] / (qm[i] * km[4] + EPSF);
        o1.y = acc[i][5] / (qm[i] * km[5] + EPSF);
        o1.z = acc[i][6] / (qm[i] * km[6] + EPSF);
        o1.w = acc[i][7] / (qm[i] * km[7] + EPSF);
        *(float4*)&C[base] = o0;
        *(float4*)&C[base + 4] = o1;
    }
}

// ---------------- top-64 (screen -> double rescore -> select) + softmax + gather ---------
__global__ void __launch_bounds__(256)
topk_kernel(const float* __restrict__ scores,
            const float* __restrict__ qbuf,
            const float* __restrict__ keys,
            const double* __restrict__ qmagd,
            const double* __restrict__ kmagd,
            const float* __restrict__ values,
            float* __restrict__ ret)
{
    __shared__ int    hist[NBINS];
    __shared__ int    csum[256];
    __shared__ float  qs[TWO_D];
    __shared__ double cand_d[CAP];
    __shared__ int    cand_i[CAP];
    __shared__ int    s_cnt;
    __shared__ int    s_thresh;
    __shared__ double sel_d[TOPK];
    __shared__ int    sel_i[TOPK];
    __shared__ float  s_w[TOPK];
    __shared__ double redv[8];
    __shared__ int    redi[8];

    const int q = blockIdx.x;
    const int tid = threadIdx.x;
    const float* row = scores + (size_t)q * NKEYS;

    for (int i = tid; i < NBINS; i += 256) hist[i] = 0;
    for (int i = tid; i < TWO_D; i += 256) qs[i] = qbuf[(size_t)q * TWO_D + i];
    if (tid == 0) s_cnt = 0;
    __syncthreads();

    for (int i = tid; i < NKEYS; i += 256) {
        float s = row[i];
        int b = (int)floorf((s + 1.0f) * 1024.0f);
        b = max(0, min(NBINS - 1, b));
        atomicAdd(&hist[b], 1);
    }
    __syncthreads();

    // suffix scan to find threshold bin (count >= TOPK), then widen by 1 bin margin
    {
        int c = 0;
#pragma unroll
        for (int j = 0; j < 8; j++) c += hist[tid * 8 + j];
        csum[tid] = c;
    }
    __syncthreads();
    if (tid == 0) {
        int acc = 0, thr = 0;
        for (int ch = 255; ch >= 0; ch--) {
            if (acc + csum[ch] >= TOPK) {
                for (int b = ch * 8 + 7; b >= ch * 8; b--) {
                    acc += hist[b];
                    if (acc >= TOPK) { thr = b; break; }
                }
                break;
            }
            acc += csum[ch];
        }
        s_thresh = max(thr - 1, 0);   // margin: fp32 screen error << 1 bin
    }
    __syncthreads();
    const int thresh = s_thresh;

    for (int i = tid; i < NKEYS; i += 256) {
        float s = row[i];
        int b = (int)floorf((s + 1.0f) * 1024.0f);
        b = max(0, min(NBINS - 1, b));
        if (b >= thresh) {
            int pos = atomicAdd(&s_cnt, 1);
            if (pos < CAP) cand_i[pos] = i;
        }
    }
    __syncthreads();
    const int cnt = min(s_cnt, CAP);

    // ---- double-precision rescore of candidates (one warp per candidate) ----
    {
        const int wid = tid >> 5, lane = tid & 31;
        const double qm = qmagd[q];
        for (int c = wid; c < cnt; c += 8) {
            const int ki = cand_i[c];
            const float* kr = keys + (size_t)ki * TWO_D;
            double acc = 0.0;
#pragma unroll
            for (int t = 0; t < 8; t++) {
                int e = t * 128 + lane * 4;
                float4 kv = *(const float4*)(kr + e);
                acc += (double)qs[e]     * (double)kv.x;
                acc += (double)qs[e + 1] * (double)kv.y;
                acc += (double)qs[e + 2] * (double)kv.z;
                acc += (double)qs[e + 3] * (double)kv.w;
            }
#pragma unroll
            for (int o = 16; o > 0; o >>= 1)
                acc += __shfl_down_sync(0xffffffffu, acc, o);
            if (lane == 0) cand_d[c] = acc / (qm * kmagd[ki] + (double)EPSF);
        }
    }
    __syncthreads();

    // ---- exact top-64 by repeated block argmax on double scores ----
    for (int t = 0; t < TOPK; t++) {
        double bv = -1e300; int bi = 0;
        for (int i = tid; i < cnt; i += 256) {
            double v = cand_d[i];
            if (v > bv) { bv = v; bi = i; }
        }
#pragma unroll
        for (int o = 16; o > 0; o >>= 1) {
            double ov = __shfl_down_sync(0xffffffffu, bv, o);
            int    oi = __shfl_down_sync(0xffffffffu, bi, o);
            if (ov > bv) { bv = ov; bi = oi; }
        }
        if ((tid & 31) == 0) { redv[tid >> 5] = bv; redi[tid >> 5] = bi; }
        __syncthreads();
        if (tid == 0) {
            double fv = redv[0]; int fi = redi[0];
#pragma unroll
            for (int w = 1; w < 8; w++)
                if (redv[w] > fv) { fv = redv[w]; fi = redi[w]; }
            sel_d[t] = fv; sel_i[t] = cand_i[fi];
            cand_d[fi] = -1e300;
        }
        __syncthreads();
    }

    // softmax over selected (sel_d[0] is the max)
    if (tid == 0) {
        float m = (float)sel_d[0];
        float z = 0.f;
        for (int t = 0; t < TOPK; t++) { float w = expf((float)sel_d[t] - m); s_w[t] = w; z += w; }
        float inv = 1.0f / z;
        for (int t = 0; t < TOPK; t++) s_w[t] *= inv;
    }
    __syncthreads();

    // weighted gather: each thread owns 4 contiguous floats of the 1024-wide row
    const int col = tid * 4;
    float4 acc = make_float4(0.f, 0.f, 0.f, 0.f);
    for (int t = 0; t < TOPK; t++) {
        const float4 v = *(const float4*)&values[(size_t)sel_i[t] * TWO_D + col];
        float w = s_w[t];
        acc.x += w * v.x; acc.y += w * v.y; acc.z += w * v.z; acc.w += w * v.w;
    }
    *(float4*)&ret[(size_t)q * TWO_D + col] = acc;
}

// ---------------- phase norm: x * gamma[d] / rms(row) ----------------
__global__ void __launch_bounds__(256)
norm_kernel(const float* __restrict__ ret, const float* __restrict__ gamma,
            float* __restrict__ out)
{
    __shared__ float sm[256];
    __shared__ float s_inv;
    const int q = blockIdx.x;
    const int tid = threadIdx.x;
    const float* p = ret + (size_t)q * TWO_D;
    float s = 0.f;
    for (int i = tid; i < TWO_D; i += 256) { float v = p[i]; s += v * v; }
    sm[tid] = s;
    __syncthreads();
    for (int o = 128; o > 0; o >>= 1) {
        if (tid < o) sm[tid] += sm[tid + o];
        __syncthreads();
    }
    if (tid == 0) {
        float mean = sm[0] / (float)DIM;
        s_inv = 1.0f / sqrtf(mean + EPSF);
    }
    __syncthreads();
    const float inv = s_inv;
    for (int i = tid; i < TWO_D; i += 256) {
        int d = i >> 1;
        out[(size_t)q * TWO_D + i] = p[i] * gamma[d] * inv;
    }
}

// ---------------- launch ----------------
extern "C" void kernel_launch(void* const* d_in, const int* in_sizes, int n_in,
                              void* d_out, int out_size)
{
    const float* query = (const float*)d_in[0];
    const float* keys  = (const float*)d_in[1];
    const float* vals  = (const float*)d_in[2];
    const float* Wq_r  = (const float*)d_in[3];
    const float* Wq_i  = (const float*)d_in[4];
    const float* bq_r  = (const float*)d_in[5];
    const float* bq_i  = (const float*)d_in[6];
    const float* Wo_r  = (const float*)d_in[7];
    const float* Wo_i  = (const float*)d_in[8];
    const float* bo_r  = (const float*)d_in[9];
    const float* bo_i  = (const float*)d_in[10];
    const float* gamma = (const float*)d_in[11];
    float* out = (float*)d_out;

    void *p_q, *p_qmd, *p_qmf, *p_kmd, *p_kmf, *p_sc, *p_ret, *p_nrm;
    cudaGetSymbolAddress(&p_q,   g_q);
    cudaGetSymbolAddress(&p_qmd, g_qmagd);
    cudaGetSymbolAddress(&p_qmf, g_qmagf);
    cudaGetSymbolAddress(&p_kmd, g_kmagd);
    cudaGetSymbolAddress(&p_kmf, g_kmagf);
    cudaGetSymbolAddress(&p_sc,  g_scores);
    cudaGetSymbolAddress(&p_ret, g_ret);
    cudaGetSymbolAddress(&p_nrm, g_norm);
    float*  qbuf  = (float*)p_q;
    double* qmagd = (double*)p_qmd;
    float*  qmagf = (float*)p_qmf;
    double* kmagd = (double*)p_kmd;
    float*  kmagf = (float*)p_kmf;
    float*  sc    = (float*)p_sc;
    float*  retb  = (float*)p_ret;
    float*  nrmb  = (float*)p_nrm;

    dim3 gproj(DIM / 64, QROWS / 64);
    cproj_kernel<true><<<gproj, 256>>>(query, Wq_r, Wq_i, bq_r, bq_i, qbuf);
    magd_kernel<<<QROWS, 128>>>(qbuf, qmagd, qmagf);
    magd_kernel<<<NKEYS, 128>>>(keys, kmagd, kmagf);

    dim3 ggemm(NKEYS / 128, QROWS / 128);
    coh_gemm_kernel<<<ggemm, 256>>>(qbuf, keys, qmagf, kmagf, sc);

    topk_kernel<<<QROWS, 256>>>(sc, qbuf, keys, qmagd, kmagd, vals, retb);
    norm_kernel<<<QROWS, 256>>>(retb, gamma, nrmb);

    cproj_kernel<false><<<gproj, 256>>>(nrmb, Wo_r, Wo_i, bo_r, bo_i, out);
}

// round 4
// speedup vs baseline: 1.8696x; 1.8696x over previous
#include <cuda_runtime.h>
#include <cuda_bf16.h>
#include <math.h>
#include <stdint.h>

#define QROWS 4096
#define DIM   512
#define TWO_D 1024
#define NKEYS 32768
#define TOPK  64
#define EPSF  1e-8f
#define NBINS 2048
#define CAP   1024

// ---- mma.sync GEMM config ----
#define GTM 128
#define GTN 128
#define GKC 64                    // bf16 per k-chunk = 128B per row
#define PITCH 72                  // bf16 elems per smem row (144B -> 4-bank step, conflict-free)
#define TILE_BYTES (128 * 144)    // 18432 per operand tile
#define STAGE_BYTES (2 * TILE_BYTES)
#define GEMM_SMEM (2 * STAGE_BYTES)   // 73728, double buffered
#define KCHUNKS (TWO_D / GKC)     // 16

// ---------------- scratch (no allocations allowed) ----------------
__device__ float  g_q[(size_t)QROWS * TWO_D];        // projected q, interleaved [Q, D, 2]
__device__ __nv_bfloat16 g_qh[(size_t)QROWS * TWO_D];
__device__ __nv_bfloat16 g_kh[(size_t)NKEYS * TWO_D];
__device__ double g_qmagd[QROWS];
__device__ float  g_qmagf[QROWS];
__device__ double g_kmagd[NKEYS];
__device__ float  g_kmagf[NKEYS];
__device__ float  g_scores[(size_t)QROWS * NKEYS];   // 512 MB coherence matrix
__device__ float  g_ret[(size_t)QROWS * TWO_D];      // retrieved
__device__ float  g_norm[(size_t)QROWS * TWO_D];     // phase-normed

// ---------------- helpers ----------------
__device__ __forceinline__ uint32_t smem_u32(const void* p) {
    uint32_t a;
    asm("{ .reg .u64 t; cvta.to.shared.u64 t, %1; cvt.u32.u64 %0, t; }" : "=r"(a) : "l"(p));
    return a;
}
__device__ __forceinline__ void cpasync16(uint32_t dst, const void* src) {
    asm volatile("cp.async.cg.shared.global [%0], [%1], 16;" :: "r"(dst), "l"(src) : "memory");
}
__device__ __forceinline__ void ldmx4(uint32_t* r, uint32_t a) {
    asm volatile("ldmatrix.sync.aligned.m8n8.x4.shared.b16 {%0,%1,%2,%3}, [%4];"
                 : "=r"(r[0]), "=r"(r[1]), "=r"(r[2]), "=r"(r[3]) : "r"(a));
}
__device__ __forceinline__ void ldmx2(uint32_t* r, uint32_t a) {
    asm volatile("ldmatrix.sync.aligned.m8n8.x2.shared.b16 {%0,%1}, [%2];"
                 : "=r"(r[0]), "=r"(r[1]) : "r"(a));
}
__device__ __forceinline__ void mma_bf16(float* d, const uint32_t* a, const uint32_t* b) {
    asm volatile(
        "mma.sync.aligned.m16n8k16.row.col.f32.bf16.bf16.f32 "
        "{%0,%1,%2,%3}, {%4,%5,%6,%7}, {%8,%9}, {%0,%1,%2,%3};"
        : "+f"(d[0]), "+f"(d[1]), "+f"(d[2]), "+f"(d[3])
        : "r"(a[0]), "r"(a[1]), "r"(a[2]), "r"(a[3]), "r"(b[0]), "r"(b[1]));
}

// Kahan add, rounding-mode-pinned so fast-math/contraction cannot break it
__device__ __forceinline__ void kadd(float& s, float& c, float t) {
    float y = __fsub_rn(t, c);
    float u = __fadd_rn(s, y);
    c = __fsub_rn(__fsub_rn(u, s), y);
    s = u;
}

// ---------------- f32 -> bf16 conversion ----------------
__global__ void __launch_bounds__(256)
cvt_bf16_kernel(const float* __restrict__ in, __nv_bfloat16* __restrict__ out)
{
    size_t i = ((size_t)blockIdx.x * 256 + threadIdx.x) * 4;
    float4 v = *(const float4*)(in + i);
    __nv_bfloat162 p0 = __float22bfloat162_rn(make_float2(v.x, v.y));
    __nv_bfloat162 p1 = __float22bfloat162_rn(make_float2(v.z, v.w));
    *(__nv_bfloat162*)(out + i)     = p0;
    *(__nv_bfloat162*)(out + i + 2) = p1;
}

// ---------------- complex projection: Y = phase_linear(X, W, b) ----------------
template <bool PRECISE>
__global__ void __launch_bounds__(256)
cproj_kernel(const float* __restrict__ X,
             const float* __restrict__ Wr, const float* __restrict__ Wi,
             const float* __restrict__ br, const float* __restrict__ bi,
             float* __restrict__ Y)
{
    __shared__ float2 Xs[16][64];
    __shared__ float2 Ws[16][64];
    const int tid = threadIdx.x;
    const int m0 = blockIdx.y * 64;
    const int n0 = blockIdx.x * 64;
    const int kk = tid & 15;
    const int rr = tid >> 4;
    const int ty4 = (tid >> 4) * 4;
    const int tx4 = (tid & 15) * 4;

    float cr[4][4], ci[4][4], er[4][4], ei[4][4];
#pragma unroll
    for (int i = 0; i < 4; i++)
#pragma unroll
        for (int j = 0; j < 4; j++) { cr[i][j] = 0.f; ci[i][j] = 0.f; er[i][j] = 0.f; ei[i][j] = 0.f; }

    for (int k0 = 0; k0 < DIM; k0 += 16) {
#pragma unroll
        for (int r = 0; r < 4; r++) {
            int row = rr + r * 16;
            Xs[kk][row] = *(const float2*)&X[((size_t)(m0 + row) * DIM + k0 + kk) * 2];
            float wr = Wr[(size_t)(n0 + row) * DIM + k0 + kk];
            float wi = Wi[(size_t)(n0 + row) * DIM + k0 + kk];
            Ws[kk][row] = make_float2(wr, wi);
        }
        __syncthreads();
#pragma unroll
        for (int k = 0; k < 16; k++) {
            float2 a[4], w[4];
#pragma unroll
            for (int i = 0; i < 4; i++) a[i] = Xs[k][ty4 + i];
#pragma unroll
            for (int j = 0; j < 4; j++) w[j] = Ws[k][tx4 + j];
#pragma unroll
            for (int i = 0; i < 4; i++)
#pragma unroll
                for (int j = 0; j < 4; j++) {
                    if (PRECISE) {
                        kadd(cr[i][j], er[i][j],  __fmul_rn(a[i].x, w[j].x));
                        kadd(cr[i][j], er[i][j], -__fmul_rn(a[i].y, w[j].y));
                        kadd(ci[i][j], ei[i][j],  __fmul_rn(a[i].x, w[j].y));
                        kadd(ci[i][j], ei[i][j],  __fmul_rn(a[i].y, w[j].x));
                    } else {
                        cr[i][j] += a[i].x * w[j].x;
                        cr[i][j] -= a[i].y * w[j].y;
                        ci[i][j] += a[i].x * w[j].y;
                        ci[i][j] += a[i].y * w[j].x;
                    }
                }
        }
        __syncthreads();
    }
#pragma unroll
    for (int i = 0; i < 4; i++) {
        int m = m0 + ty4 + i;
#pragma unroll
        for (int j = 0; j < 4; j++) {
            int n = n0 + tx4 + j;
            float vr = PRECISE ? __fadd_rn(cr[i][j], er[i][j]) : cr[i][j];
            float vi = PRECISE ? __fadd_rn(ci[i][j], ei[i][j]) : ci[i][j];
            Y[((size_t)m * DIM + n) * 2 + 0] = vr + br[n];
            Y[((size_t)m * DIM + n) * 2 + 1] = vi + bi[n];
        }
    }
}

// ---------------- magnitude (double): sqrt(sum x^2 + EPS) ----------------
__global__ void magd_kernel(const float* __restrict__ X,
                            double* __restrict__ out_d, float* __restrict__ out_f)
{
    __shared__ double sm[128];
    int row = blockIdx.x;
    const float* p = X + (size_t)row * TWO_D;
    double s = 0.0;
    for (int i = threadIdx.x; i < TWO_D; i += 128) { double v = (double)p[i]; s += v * v; }
    sm[threadIdx.x] = s;
    __syncthreads();
    for (int o = 64; o > 0; o >>= 1) {
        if (threadIdx.x < o) sm[threadIdx.x] += sm[threadIdx.x + o];
        __syncthreads();
    }
    if (threadIdx.x == 0) {
        double m = sqrt(sm[0] + 1e-8);
        out_d[row] = m;
        out_f[row] = (float)m;
    }
}

// ---------------- bf16 mma.sync screening GEMM ----------------
// C[q,n] = (A[q,:]·B[n,:]) / (qmag[q]*kmag[n] + EPS)
// A: g_qh [4096,1024] bf16 row-major, B: g_kh [32768,1024] bf16 row-major.
// Tile 128x128, k-chunk 64, double-buffered cp.async, 8 warps (2m x 4n), warp tile 64x32.
__device__ __forceinline__ void gemm_load_stage(
    const char* Abase, const char* Bbase, uint32_t sb, int tid, int it, int s)
{
    const int seg = tid & 7;
    const size_t koff = (size_t)it * 128 + (size_t)seg * 16;
    const uint32_t so = sb + (uint32_t)s * STAGE_BYTES;
#pragma unroll
    for (int j = 0; j < 4; j++) {
        int row = (tid >> 3) + 32 * j;
        cpasync16(so + row * 144 + seg * 16, Abase + (size_t)row * 2048 + koff);
    }
#pragma unroll
    for (int j = 0; j < 4; j++) {
        int row = (tid >> 3) + 32 * j;
        cpasync16(so + TILE_BYTES + row * 144 + seg * 16, Bbase + (size_t)row * 2048 + koff);
    }
    asm volatile("cp.async.commit_group;" ::: "memory");
}

__global__ void __launch_bounds__(256, 2)
coh_gemm_mma(const __nv_bfloat16* __restrict__ A, const __nv_bfloat16* __restrict__ B,
             const float* __restrict__ qmag, const float* __restrict__ kmag,
             float* __restrict__ C)
{
    extern __shared__ __align__(16) char smraw[];
    const uint32_t sb = smem_u32(smraw);
    const int tid = threadIdx.x;
    const int wid = tid >> 5, lane = tid & 31;
    const int m0 = blockIdx.x * GTM;     // m fastest -> B tile shared by 32 consecutive CTAs
    const int n0 = blockIdx.y * GTN;
    const int wm0 = (wid & 1) * 64, wn0 = (wid >> 1) * 32;

    float acc[4][4][4];
#pragma unroll
    for (int a = 0; a < 4; a++)
#pragma unroll
        for (int b = 0; b < 4; b++)
#pragma unroll
            for (int c = 0; c < 4; c++) acc[a][b][c] = 0.f;

    const char* Abase = (const char*)A + (size_t)m0 * 2048;
    const char* Bbase = (const char*)B + (size_t)n0 * 2048;

    gemm_load_stage(Abase, Bbase, sb, tid, 0, 0);
    int buf = 0;
    const int arow = lane & 15, acol = (lane >> 4) * 8;
    const int brow = lane & 7,  bcol = ((lane >> 3) & 1) * 8;

    for (int it = 0; it < KCHUNKS; it++) {
        if (it < KCHUNKS - 1) {
            gemm_load_stage(Abase, Bbase, sb, tid, it + 1, buf ^ 1);
            asm volatile("cp.async.wait_group 1;" ::: "memory");
        } else {
            asm volatile("cp.async.wait_group 0;" ::: "memory");
        }
        __syncthreads();
        const uint32_t aB = sb + (uint32_t)buf * STAGE_BYTES;
        const uint32_t bB = aB + TILE_BYTES;
#pragma unroll
        for (int ks = 0; ks < 4; ks++) {
            uint32_t afr[4][4], bfr[4][2];
#pragma unroll
            for (int fm = 0; fm < 4; fm++)
                ldmx4(afr[fm], aB + (wm0 + fm * 16 + arow) * 144 + (ks * 16 + acol) * 2);
#pragma unroll
            for (int fn = 0; fn < 4; fn++)
                ldmx2(bfr[fn], bB + (wn0 + fn * 8 + brow) * 144 + (ks * 16 + bcol) * 2);
#pragma unroll
            for (int fm = 0; fm < 4; fm++)
#pragma unroll
                for (int fn = 0; fn < 4; fn++)
                    mma_bf16(acc[fm][fn], afr[fm], bfr[fn]);
        }
        __syncthreads();
        buf ^= 1;
    }

    // epilogue: normalize + store
#pragma unroll
    for (int fm = 0; fm < 4; fm++) {
        int mlo = m0 + wm0 + fm * 16 + (lane >> 2);
        int mhi = mlo + 8;
        float qlo = qmag[mlo], qhi = qmag[mhi];
#pragma unroll
        for (int fn = 0; fn < 4; fn++) {
            int n = n0 + wn0 + fn * 8 + (lane & 3) * 2;
            float k0v = kmag[n], k1v = kmag[n + 1];
            float2 vlo, vhi;
            vlo.x = acc[fm][fn][0] / (qlo * k0v + EPSF);
            vlo.y = acc[fm][fn][1] / (qlo * k1v + EPSF);
            vhi.x = acc[fm][fn][2] / (qhi * k0v + EPSF);
            vhi.y = acc[fm][fn][3] / (qhi * k1v + EPSF);
            *(float2*)&C[(size_t)mlo * NKEYS + n] = vlo;
            *(float2*)&C[(size_t)mhi * NKEYS + n] = vhi;
        }
    }
}

// ---------------- top-64 (screen -> double rescore -> select) + softmax + gather ---------
__global__ void __launch_bounds__(256)
topk_kernel(const float* __restrict__ scores,
            const float* __restrict__ qbuf,
            const float* __restrict__ keys,
            const double* __restrict__ qmagd,
            const double* __restrict__ kmagd,
            const float* __restrict__ values,
            float* __restrict__ ret)
{
    __shared__ int    hist[NBINS];
    __shared__ int    csum[256];
    __shared__ float  qs[TWO_D];
    __shared__ double cand_d[CAP];
    __shared__ int    cand_i[CAP];
    __shared__ int    s_cnt;
    __shared__ int    s_thresh;
    __shared__ double sel_d[TOPK];
    __shared__ int    sel_i[TOPK];
    __shared__ float  s_w[TOPK];
    __shared__ double redv[8];
    __shared__ int    redi[8];

    const int q = blockIdx.x;
    const int tid = threadIdx.x;
    const float* row = scores + (size_t)q * NKEYS;

    for (int i = tid; i < NBINS; i += 256) hist[i] = 0;
    for (int i = tid; i < TWO_D; i += 256) qs[i] = qbuf[(size_t)q * TWO_D + i];
    if (tid == 0) s_cnt = 0;
    __syncthreads();

    for (int i = tid; i < NKEYS; i += 256) {
        float s = row[i];
        int b = (int)floorf((s + 1.0f) * 1024.0f);
        b = max(0, min(NBINS - 1, b));
        atomicAdd(&hist[b], 1);
    }
    __syncthreads();

    {
        int c = 0;
#pragma unroll
        for (int j = 0; j < 8; j++) c += hist[tid * 8 + j];
        csum[tid] = c;
    }
    __syncthreads();
    if (tid == 0) {
        int acc = 0, thr = 0;
        for (int ch = 255; ch >= 0; ch--) {
            if (acc + csum[ch] >= TOPK) {
                for (int b = ch * 8 + 7; b >= ch * 8; b--) {
                    acc += hist[b];
                    if (acc >= TOPK) { thr = b; break; }
                }
                break;
            }
            acc += csum[ch];
        }
        s_thresh = max(thr - 2, 0);   // 2-bin margin (1.95e-3) >> bf16 screen error (~1e-4)
    }
    __syncthreads();
    const int thresh = s_thresh;

    for (int i = tid; i < NKEYS; i += 256) {
        float s = row[i];
        int b = (int)floorf((s + 1.0f) * 1024.0f);
        b = max(0, min(NBINS - 1, b));
        if (b >= thresh) {
            int pos = atomicAdd(&s_cnt, 1);
            if (pos < CAP) cand_i[pos] = i;
        }
    }
    __syncthreads();
    const int cnt = min(s_cnt, CAP);

    // ---- double-precision rescore of candidates (one warp per candidate) ----
    {
        const int wid = tid >> 5, lane = tid & 31;
        const double qm = qmagd[q];
        for (int c = wid; c < cnt; c += 8) {
            const int ki = cand_i[c];
            const float* kr = keys + (size_t)ki * TWO_D;
            double acc = 0.0;
#pragma unroll
            for (int t = 0; t < 8; t++) {
                int e = t * 128 + lane * 4;
                float4 kv = *(const float4*)(kr + e);
                acc += (double)qs[e]     * (double)kv.x;
                acc += (double)qs[e + 1] * (double)kv.y;
                acc += (double)qs[e + 2] * (double)kv.z;
                acc += (double)qs[e + 3] * (double)kv.w;
            }
#pragma unroll
            for (int o = 16; o > 0; o >>= 1)
                acc += __shfl_down_sync(0xffffffffu, acc, o);
            if (lane == 0) cand_d[c] = acc / (qm * kmagd[ki] + (double)EPSF);
        }
    }
    __syncthreads();

    for (int t = 0; t < TOPK; t++) {
        double bv = -1e300; int bi = 0;
        for (int i = tid; i < cnt; i += 256) {
            double v = cand_d[i];
            if (v > bv) { bv = v; bi = i; }
        }
#pragma unroll
        for (int o = 16; o > 0; o >>= 1) {
            double ov = __shfl_down_sync(0xffffffffu, bv, o);
            int    oi = __shfl_down_sync(0xffffffffu, bi, o);
            if (ov > bv) { bv = ov; bi = oi; }
        }
        if ((tid & 31) == 0) { redv[tid >> 5] = bv; redi[tid >> 5] = bi; }
        __syncthreads();
        if (tid == 0) {
            double fv = redv[0]; int fi = redi[0];
#pragma unroll
            for (int w = 1; w < 8; w++)
                if (redv[w] > fv) { fv = redv[w]; fi = redi[w]; }
            sel_d[t] = fv; sel_i[t] = cand_i[fi];
            cand_d[fi] = -1e300;
        }
        __syncthreads();
    }

    if (tid == 0) {
        float m = (float)sel_d[0];
        float z = 0.f;
        for (int t = 0; t < TOPK; t++) { float w = expf((float)sel_d[t] - m); s_w[t] = w; z += w; }
        float inv = 1.0f / z;
        for (int t = 0; t < TOPK; t++) s_w[t] *= inv;
    }
    __syncthreads();

    const int col = tid * 4;
    float4 acc = make_float4(0.f, 0.f, 0.f, 0.f);
    for (int t = 0; t < TOPK; t++) {
        const float4 v = *(const float4*)&values[(size_t)sel_i[t] * TWO_D + col];
        float w = s_w[t];
        acc.x += w * v.x; acc.y += w * v.y; acc.z += w * v.z; acc.w += w * v.w;
    }
    *(float4*)&ret[(size_t)q * TWO_D + col] = acc;
}

// ---------------- phase norm: x * gamma[d] / rms(row) ----------------
__global__ void __launch_bounds__(256)
norm_kernel(const float* __restrict__ ret, const float* __restrict__ gamma,
            float* __restrict__ out)
{
    __shared__ float sm[256];
    __shared__ float s_inv;
    const int q = blockIdx.x;
    const int tid = threadIdx.x;
    const float* p = ret + (size_t)q * TWO_D;
    float s = 0.f;
    for (int i = tid; i < TWO_D; i += 256) { float v = p[i]; s += v * v; }
    sm[tid] = s;
    __syncthreads();
    for (int o = 128; o > 0; o >>= 1) {
        if (tid < o) sm[tid] += sm[tid + o];
        __syncthreads();
    }
    if (tid == 0) {
        float mean = sm[0] / (float)DIM;
        s_inv = 1.0f / sqrtf(mean + EPSF);
    }
    __syncthreads();
    const float inv = s_inv;
    for (int i = tid; i < TWO_D; i += 256) {
        int d = i >> 1;
        out[(size_t)q * TWO_D + i] = p[i] * gamma[d] * inv;
    }
}

// ---------------- launch ----------------
extern "C" void kernel_launch(void* const* d_in, const int* in_sizes, int n_in,
                              void* d_out, int out_size)
{
    const float* query = (const float*)d_in[0];
    const float* keys  = (const float*)d_in[1];
    const float* vals  = (const float*)d_in[2];
    const float* Wq_r  = (const float*)d_in[3];
    const float* Wq_i  = (const float*)d_in[4];
    const float* bq_r  = (const float*)d_in[5];
    const float* bq_i  = (const float*)d_in[6];
    const float* Wo_r  = (const float*)d_in[7];
    const float* Wo_i  = (const float*)d_in[8];
    const float* bo_r  = (const float*)d_in[9];
    const float* bo_i  = (const float*)d_in[10];
    const float* gamma = (const float*)d_in[11];
    float* out = (float*)d_out;

    void *p_q, *p_qh, *p_kh, *p_qmd, *p_qmf, *p_kmd, *p_kmf, *p_sc, *p_ret, *p_nrm;
    cudaGetSymbolAddress(&p_q,   g_q);
    cudaGetSymbolAddress(&p_qh,  g_qh);
    cudaGetSymbolAddress(&p_kh,  g_kh);
    cudaGetSymbolAddress(&p_qmd, g_qmagd);
    cudaGetSymbolAddress(&p_qmf, g_qmagf);
    cudaGetSymbolAddress(&p_kmd, g_kmagd);
    cudaGetSymbolAddress(&p_kmf, g_kmagf);
    cudaGetSymbolAddress(&p_sc,  g_scores);
    cudaGetSymbolAddress(&p_ret, g_ret);
    cudaGetSymbolAddress(&p_nrm, g_norm);
    float*  qbuf  = (float*)p_q;
    __nv_bfloat16* qh = (__nv_bfloat16*)p_qh;
    __nv_bfloat16* kh = (__nv_bfloat16*)p_kh;
    double* qmagd = (double*)p_qmd;
    float*  qmagf = (float*)p_qmf;
    double* kmagd = (double*)p_kmd;
    float*  kmagf = (float*)p_kmf;
    float*  sc    = (float*)p_sc;
    float*  retb  = (float*)p_ret;
    float*  nrmb  = (float*)p_nrm;

    cudaFuncSetAttribute(coh_gemm_mma, cudaFuncAttributeMaxDynamicSharedMemorySize, GEMM_SMEM);

    dim3 gproj(DIM / 64, QROWS / 64);
    cproj_kernel<true><<<gproj, 256>>>(query, Wq_r, Wq_i, bq_r, bq_i, qbuf);
    magd_kernel<<<QROWS, 128>>>(qbuf, qmagd, qmagf);
    magd_kernel<<<NKEYS, 128>>>(keys, kmagd, kmagf);

    cvt_bf16_kernel<<<((size_t)QROWS * TWO_D) / (256 * 4), 256>>>(qbuf, qh);
    cvt_bf16_kernel<<<((size_t)NKEYS * TWO_D) / (256 * 4), 256>>>(keys, kh);

    dim3 ggemm(QROWS / GTM, NKEYS / GTN);
    coh_gemm_mma<<<ggemm, 256, GEMM_SMEM>>>(qh, kh, qmagf, kmagf, sc);

    topk_kernel<<<QROWS, 256>>>(sc, qbuf, keys, qmagd, kmagd, vals, retb);
    norm_kernel<<<QROWS, 256>>>(retb, gamma, nrmb);

    cproj_kernel<false><<<gproj, 256>>>(nrmb, Wo_r, Wo_i, bo_r, bo_i, out);
}